// round 7
// baseline (speedup 1.0000x reference)
#include <cuda_runtime.h>
#include <cstdint>

// ---------------------------------------------------------------------------
// fp4 (bitsandbytes) dequant + GEMV:  y[4, M] = x[4, N] @ W[M, N]^T + bias
//   qweight: numel/2 int32, each holding ONE byte (two nibbles, hi first)
//   absmax : per-64-element block scale; code: 16-entry codebook
//
// R5 mapping (best measured): a warp owns a contiguous 64-n "step"; lane l
// takes the packed byte at int32 index (step*32 + l), i.e. n = 2l, 2l+1.
// x loads are LDG.64 lane-consecutive, absmax is warp-uniform per step.
// 4 rows/warp, 4 warps/block, N split in 2 halves (grid 2 x 512 = 1024).
//
// Fused finish (threadfence reduction): both split-blocks of a row-group
// write partials to g_part; the LAST one (device counter) sums both halves
// + bias and writes out directly. Counter reset to 0 for graph replays.
// ---------------------------------------------------------------------------

constexpr int MD = 8192, ND = 8192;
constexpr int NSPLIT = 2;
constexpr int NHALF  = ND / NSPLIT;     // 4096 n per block
constexpr int STEPS  = NHALF / 64;      // 64 steps (one absmax block each)
constexpr int RW = 4;                   // rows per warp
constexpr int WPB = 4;                  // warps per block (128 threads)
constexpr int RPB = RW * WPB;           // 16 rows per block

__device__ float g_part[NSPLIT * 4 * MD];        // [split][batch][row]
__device__ unsigned int g_cnt[MD / RPB];         // zero-init; reset after use

static __device__ __forceinline__ unsigned long long pk2(float lo, float hi) {
    unsigned long long r;
    asm("mov.b64 %0, {%1, %2};" : "=l"(r) : "f"(lo), "f"(hi));
    return r;
}
static __device__ __forceinline__ void up2(unsigned long long v, float& lo, float& hi) {
    asm("mov.b64 {%0, %1}, %2;" : "=f"(lo), "=f"(hi) : "l"(v));
}
static __device__ __forceinline__ unsigned long long f2fma(unsigned long long a,
                                                           unsigned long long b,
                                                           unsigned long long c) {
    unsigned long long d;
    asm("fma.rn.f32x2 %0, %1, %2, %3;" : "=l"(d) : "l"(a), "l"(b), "l"(c));
    return d;
}
static __device__ __forceinline__ unsigned long long f2add(unsigned long long a,
                                                           unsigned long long b) {
    unsigned long long d;
    asm("add.rn.f32x2 %0, %1, %2;" : "=l"(d) : "l"(a), "l"(b));
    return d;
}

__global__ void __launch_bounds__(128, 8)
fp4_main(const float* __restrict__ x, const int* __restrict__ qw,
         const float* __restrict__ am, const float* __restrict__ code,
         const float* __restrict__ bias, float* __restrict__ out)
{
    const int lane = threadIdx.x & 31;
    const int wid  = threadIdx.x >> 5;
    const int split = blockIdx.x;              // 0 or 1
    const int row0  = blockIdx.y * RPB + wid * RW;
    const int n0    = split * NHALF;

    // Register-resident codebook: lane l holds code[l & 15]; decode via shfl.
    const float creg = code[lane & 15];

    // Per-row streams for this N-half.
    const int*   q0  = qw + row0 * (ND / 2)  + split * (NHALF / 2);
    const float* am0 = am + row0 * (ND / 64) + split * (NHALF / 64);
    const float2* x0 = reinterpret_cast<const float2*>(x + 0 * ND + n0);
    const float2* x1 = reinterpret_cast<const float2*>(x + 1 * ND + n0);
    const float2* x2 = reinterpret_cast<const float2*>(x + 2 * ND + n0);
    const float2* x3 = reinterpret_cast<const float2*>(x + 3 * ND + n0);

    unsigned long long a01[RW] = {0, 0, 0, 0};
    unsigned long long a23[RW] = {0, 0, 0, 0};

#pragma unroll 4
    for (int step = 0; step < STEPS; ++step) {
        const int col = step * 32 + lane;      // int32 index in the half-row

        // x for this lane's two n (2*col, 2*col+1), all 4 batches. LDG.64,
        // lanes consecutive -> 2 wavefronts each.
        const float2 v0 = __ldg(&x0[col]);
        const float2 v1 = __ldg(&x1[col]);
        const float2 v2 = __ldg(&x2[col]);
        const float2 v3 = __ldg(&x3[col]);
        const unsigned long long xe01 = pk2(v0.x, v1.x);   // n even, batches 0,1
        const unsigned long long xo01 = pk2(v0.y, v1.y);   // n odd
        const unsigned long long xe23 = pk2(v2.x, v3.x);
        const unsigned long long xo23 = pk2(v2.y, v3.y);

#pragma unroll
        for (int r = 0; r < RW; r++) {
            const int   b = __ldg(q0 + r * (ND / 2) + col);        // one byte
            const float s = __ldg(am0 + r * (ND / 64) + step);     // warp-uniform
            const float chi = __shfl_sync(0xffffffffu, creg, b >> 4);   // n = 2l
            const float clo = __shfl_sync(0xffffffffu, creg, b & 15);   // n = 2l+1
            const float w0 = chi * s;
            const float w1 = clo * s;
            const unsigned long long s0 = pk2(w0, w0);
            const unsigned long long s1 = pk2(w1, w1);
            a01[r] = f2fma(s0, xe01, a01[r]);
            a01[r] = f2fma(s1, xo01, a01[r]);
            a23[r] = f2fma(s0, xe23, a23[r]);
            a23[r] = f2fma(s1, xo23, a23[r]);
        }
    }

    // Butterfly reduction over lanes (packed f32x2 adds).
#pragma unroll
    for (int r = 0; r < RW; r++) {
#pragma unroll
        for (int off = 16; off > 0; off >>= 1) {
            a01[r] = f2add(a01[r], __shfl_xor_sync(0xffffffffu, a01[r], off));
            a23[r] = f2add(a23[r], __shfl_xor_sync(0xffffffffu, a23[r], off));
        }
    }

    // Publish this split's partials.
#pragma unroll
    for (int r = 0; r < RW; r++) {
        if (lane == r) {
            const int row = row0 + r;
            float y0, y1, y2, y3;
            up2(a01[r], y0, y1);
            up2(a23[r], y2, y3);
            g_part[(split * 4 + 0) * MD + row] = y0;
            g_part[(split * 4 + 1) * MD + row] = y1;
            g_part[(split * 4 + 2) * MD + row] = y2;
            g_part[(split * 4 + 3) * MD + row] = y3;
        }
    }

    // Threadfence reduction: the last of the 2 split-blocks for this
    // row-group combines both partials + bias and writes out.
    __threadfence();
    __syncthreads();
    __shared__ bool isLast;
    if (threadIdx.x == 0) {
        const unsigned int old = atomicAdd(&g_cnt[blockIdx.y], 1u);
        isLast = (old == 1u);
    }
    __syncthreads();

    if (isLast) {
        __threadfence();   // order partner-partial loads after the flag
        const int os = (split ^ 1) * 4;   // partner split's batch base
#pragma unroll
        for (int r = 0; r < RW; r++) {
            if (lane == r) {
                const int row = row0 + r;
                float y0, y1, y2, y3;
                up2(a01[r], y0, y1);
                up2(a23[r], y2, y3);
                const float bb = bias[row];
                out[0 * MD + row] = (y0 + g_part[(os + 0) * MD + row]) + bb;
                out[1 * MD + row] = (y1 + g_part[(os + 1) * MD + row]) + bb;
                out[2 * MD + row] = (y2 + g_part[(os + 2) * MD + row]) + bb;
                out[3 * MD + row] = (y3 + g_part[(os + 3) * MD + row]) + bb;
            }
        }
        __syncthreads();
        if (threadIdx.x == 0) g_cnt[blockIdx.y] = 0u;   // ready for next replay
    }
}

extern "C" void kernel_launch(void* const* d_in, const int* in_sizes, int n_in,
                              void* d_out, int out_size)
{
    const float* x    = (const float*)d_in[0];
    const int*   qw   = (const int*)d_in[1];
    const float* am   = (const float*)d_in[2];
    const float* code = (const float*)d_in[3];
    const float* bias = (const float*)d_in[4];
    float*       out  = (float*)d_out;

    dim3 grid(NSPLIT, MD / RPB);              // (2, 512) = 1024 blocks
    fp4_main<<<grid, WPB * 32>>>(x, qw, am, code, bias, out);
}